// round 1
// baseline (speedup 1.0000x reference)
#include <cuda_runtime.h>
#include <cuda_bf16.h>
#include <math.h>

// Problem constants
#define D_MODEL 1024
#define N_HEADS 16
#define D_HEAD  64
#define D_FF    2752
#define BATCH   2
#define SEQ     2048
#define TOKENS  (BATCH * SEQ)          // 4096
#define EPSV    1e-5f

// ---------------------------------------------------------------------------
// Scratch buffers (device globals; no allocation allowed)
// ---------------------------------------------------------------------------
__device__ float g_xn  [TOKENS * D_MODEL];
__device__ float g_q   [TOKENS * D_MODEL];
__device__ float g_k   [TOKENS * D_MODEL];
__device__ float g_v   [TOKENS * D_MODEL];
__device__ float g_attn[TOKENS * D_MODEL];
__device__ float g_hres[TOKENS * D_MODEL];
__device__ float g_hn  [TOKENS * D_MODEL];
__device__ float g_ff1 [TOKENS * D_FF];
__device__ float g_ff3 [TOKENS * D_FF];

// ---------------------------------------------------------------------------
// RMSNorm: one block per row of 1024
// ---------------------------------------------------------------------------
__global__ void __launch_bounds__(256) rmsnorm_kernel(
    const float* __restrict__ x, const float* __restrict__ g,
    float* __restrict__ out)
{
    int row = blockIdx.x;
    const float* xr = x + (size_t)row * D_MODEL;
    float*       yr = out + (size_t)row * D_MODEL;
    int t = threadIdx.x;

    // each thread: 4 contiguous floats via float4
    float4 v = reinterpret_cast<const float4*>(xr)[t];
    float ss = v.x * v.x + v.y * v.y + v.z * v.z + v.w * v.w;

    // warp reduce
    #pragma unroll
    for (int o = 16; o > 0; o >>= 1)
        ss += __shfl_xor_sync(0xffffffffu, ss, o);

    __shared__ float warp_s[8];
    int lane = t & 31, wid = t >> 5;
    if (lane == 0) warp_s[wid] = ss;
    __syncthreads();
    if (wid == 0) {
        float s2 = (lane < 8) ? warp_s[lane] : 0.f;
        #pragma unroll
        for (int o = 4; o > 0; o >>= 1)
            s2 += __shfl_xor_sync(0xffffffffu, s2, o);
        if (lane == 0) warp_s[0] = s2;
    }
    __syncthreads();
    float inv = rsqrtf(warp_s[0] * (1.0f / D_MODEL) + EPSV);

    float4 gv = reinterpret_cast<const float4*>(g)[t];
    float4 o4;
    o4.x = v.x * inv * gv.x;
    o4.y = v.y * inv * gv.y;
    o4.z = v.z * inv * gv.z;
    o4.w = v.w * inv * gv.w;
    reinterpret_cast<float4*>(yr)[t] = o4;
}

// ---------------------------------------------------------------------------
// SGEMM: C[M,N] = A[M,K] @ B[K,N] (+ residual R). Row-major everything.
// 128x128 block tile, K-tile 16, 256 threads, 8x8 per-thread register tile.
// M % 128 == 0, K % 16 == 0 assumed (true for all calls). N edge guarded.
// ---------------------------------------------------------------------------
#define BM 128
#define BN 128
#define BK 16
#define TM 8
#define TN 8

template<bool ADD_RES>
__global__ void __launch_bounds__(256) sgemm_kernel(
    const float* __restrict__ A, const float* __restrict__ B,
    const float* __restrict__ R, float* __restrict__ C,
    int M, int N, int K)
{
    __shared__ float As[BK][BM];
    __shared__ float Bs[BK][BN];

    const int t  = threadIdx.x;
    const int m0 = blockIdx.y * BM;
    const int n0 = blockIdx.x * BN;
    const int tr = t >> 4;   // 0..15
    const int tc = t & 15;   // 0..15

    float acc[TM][TN];
    #pragma unroll
    for (int i = 0; i < TM; i++)
        #pragma unroll
        for (int j = 0; j < TN; j++) acc[i][j] = 0.f;

    for (int k0 = 0; k0 < K; k0 += BK) {
        // ---- load A tile (128 x 16) : 512 float4, 2 per thread, transpose to As[k][m]
        #pragma unroll
        for (int u = 0; u < 2; u++) {
            int idx = t + u * 256;
            int row = idx >> 2;          // 0..127
            int c4  = idx & 3;           // 0..3
            float4 va = *reinterpret_cast<const float4*>(
                &A[(size_t)(m0 + row) * K + k0 + c4 * 4]);
            As[c4 * 4 + 0][row] = va.x;
            As[c4 * 4 + 1][row] = va.y;
            As[c4 * 4 + 2][row] = va.z;
            As[c4 * 4 + 3][row] = va.w;
        }
        // ---- load B tile (16 x 128) : 512 float4, 2 per thread
        #pragma unroll
        for (int u = 0; u < 2; u++) {
            int idx = t + u * 256;
            int kk = idx >> 5;           // 0..15
            int n4 = idx & 31;           // 0..31
            int n  = n0 + n4 * 4;
            float4 vb = make_float4(0.f, 0.f, 0.f, 0.f);
            if (n < N)
                vb = *reinterpret_cast<const float4*>(&B[(size_t)(k0 + kk) * N + n]);
            *reinterpret_cast<float4*>(&Bs[kk][n4 * 4]) = vb;
        }
        __syncthreads();

        #pragma unroll
        for (int kk = 0; kk < BK; kk++) {
            float af[TM], bf[TN];
            #pragma unroll
            for (int i = 0; i < TM; i++) af[i] = As[kk][tr * TM + i];
            #pragma unroll
            for (int j = 0; j < TN; j++) bf[j] = Bs[kk][tc * TN + j];
            #pragma unroll
            for (int i = 0; i < TM; i++)
                #pragma unroll
                for (int j = 0; j < TN; j++)
                    acc[i][j] += af[i] * bf[j];
        }
        __syncthreads();
    }

    // ---- store (guard N)
    #pragma unroll
    for (int i = 0; i < TM; i++) {
        int row = m0 + tr * TM + i;
        #pragma unroll
        for (int j = 0; j < TN; j++) {
            int col = n0 + tc * TN + j;
            if (col < N) {
                float v = acc[i][j];
                if (ADD_RES) v += R[(size_t)row * N + col];
                C[(size_t)row * N + col] = v;
            }
        }
    }
}

// ---------------------------------------------------------------------------
// Causal flash attention, fp32.
// q,k,v layout: [b, s, h, dh] i.e. element (b*SEQ+s)*D_MODEL + h*64 + d.
// Block: 64 query rows for one (b,h). 8 warps, 8 rows per warp.
// Key tile = 32 (one score per lane). Online softmax.
// ---------------------------------------------------------------------------
#define AQ_ROWS 64
#define AK_TILE 32

__global__ void __launch_bounds__(256) attention_kernel(
    const float* __restrict__ Q, const float* __restrict__ K,
    const float* __restrict__ V, float* __restrict__ O)
{
    __shared__ float Qs[AQ_ROWS][D_HEAD];      // 16 KB
    __shared__ float Ks[AK_TILE][D_HEAD + 1];  // padded: lane-major reads
    __shared__ float Vs[AK_TILE][D_HEAD + 1];

    const int t    = threadIdx.x;
    const int lane = t & 31;
    const int w    = t >> 5;                   // warp 0..7
    const int bh   = blockIdx.y;
    const int b    = bh >> 4;                  // /16 heads
    const int h    = bh & 15;
    const int q0   = blockIdx.x * AQ_ROWS;

    const float scale = 0.125f;                // 1/sqrt(64)
    const size_t base = ((size_t)b * SEQ) * D_MODEL + (size_t)h * D_HEAD;

    // load Q tile (64 x 64)
    #pragma unroll
    for (int u = 0; u < (AQ_ROWS * D_HEAD) / 256; u++) {
        int idx = t + u * 256;
        int r = idx >> 6, d = idx & 63;
        Qs[r][d] = Q[base + (size_t)(q0 + r) * D_MODEL + d];
    }

    float m[8], l[8], acc0[8], acc1[8];
    #pragma unroll
    for (int i = 0; i < 8; i++) { m[i] = -1e30f; l[i] = 0.f; acc0[i] = 0.f; acc1[i] = 0.f; }

    const int nkt = (q0 >> 5) + 2;   // key tiles covering keys 0 .. q0+63

    for (int kt = 0; kt < nkt; kt++) {
        const int kbase = kt * AK_TILE;
        __syncthreads();
        // load K,V tiles (32 x 64 each)
        #pragma unroll
        for (int u = 0; u < (AK_TILE * D_HEAD) / 256; u++) {
            int idx = t + u * 256;
            int r = idx >> 6, d = idx & 63;
            size_t gk = base + (size_t)(kbase + r) * D_MODEL + d;
            Ks[r][d] = K[gk];
            Vs[r][d] = V[gk];
        }
        __syncthreads();

        #pragma unroll 1
        for (int i = 0; i < 8; i++) {
            const int r = w * 8 + i;
            const int qrow = q0 + r;
            // score for this lane's key
            const float* qp = &Qs[r][0];
            const float* kp = &Ks[lane][0];
            float s = 0.f;
            #pragma unroll
            for (int d = 0; d < D_HEAD; d++) s += qp[d] * kp[d];
            s *= scale;
            if (kbase + lane > qrow) s = -1e30f;

            // warp max of s
            float mt = s;
            #pragma unroll
            for (int o = 16; o > 0; o >>= 1)
                mt = fmaxf(mt, __shfl_xor_sync(0xffffffffu, mt, o));
            float mnew = fmaxf(m[i], mt);
            float p    = __expf(s - mnew);
            float corr = __expf(m[i] - mnew);
            m[i] = mnew;

            float ps = p;
            #pragma unroll
            for (int o = 16; o > 0; o >>= 1)
                ps += __shfl_xor_sync(0xffffffffu, ps, o);
            l[i] = l[i] * corr + ps;
            acc0[i] *= corr;
            acc1[i] *= corr;

            #pragma unroll
            for (int kk = 0; kk < AK_TILE; kk++) {
                float pk = __shfl_sync(0xffffffffu, p, kk);
                acc0[i] += pk * Vs[kk][lane];
                acc1[i] += pk * Vs[kk][lane + 32];
            }
        }
    }

    // write O
    #pragma unroll
    for (int i = 0; i < 8; i++) {
        const int r = w * 8 + i;
        float inv = 1.0f / l[i];
        size_t go = base + (size_t)(q0 + r) * D_MODEL;
        O[go + lane]      = acc0[i] * inv;
        O[go + lane + 32] = acc1[i] * inv;
    }
}

// ---------------------------------------------------------------------------
// SwiGLU elementwise: g_ff1 <- silu(g_ff1) * g_ff3  (float4)
// ---------------------------------------------------------------------------
__global__ void __launch_bounds__(256) swiglu_kernel(
    float* __restrict__ a, const float* __restrict__ b, int n4)
{
    int i = blockIdx.x * blockDim.x + threadIdx.x;
    if (i >= n4) return;
    float4 va = reinterpret_cast<float4*>(a)[i];
    float4 vb = reinterpret_cast<const float4*>(b)[i];
    float4 o;
    o.x = va.x / (1.f + __expf(-va.x)) * vb.x;
    o.y = va.y / (1.f + __expf(-va.y)) * vb.y;
    o.z = va.z / (1.f + __expf(-va.z)) * vb.z;
    o.w = va.w / (1.f + __expf(-va.w)) * vb.w;
    reinterpret_cast<float4*>(a)[i] = o;
}

// ---------------------------------------------------------------------------
// Launch
// ---------------------------------------------------------------------------
extern "C" void kernel_launch(void* const* d_in, const int* in_sizes, int n_in,
                              void* d_out, int out_size)
{
    const float* x   = (const float*)d_in[0];
    const float* g1  = (const float*)d_in[1];
    const float* g2  = (const float*)d_in[2];
    const float* w_q = (const float*)d_in[3];
    const float* w_k = (const float*)d_in[4];
    const float* w_v = (const float*)d_in[5];
    const float* w_o = (const float*)d_in[6];
    const float* w1  = (const float*)d_in[7];
    const float* w2  = (const float*)d_in[8];
    const float* w3  = (const float*)d_in[9];
    float* out = (float*)d_out;

    float *xn, *q, *k, *v, *attn, *hres, *hn, *ff1, *ff3;
    cudaGetSymbolAddress((void**)&xn,   g_xn);
    cudaGetSymbolAddress((void**)&q,    g_q);
    cudaGetSymbolAddress((void**)&k,    g_k);
    cudaGetSymbolAddress((void**)&v,    g_v);
    cudaGetSymbolAddress((void**)&attn, g_attn);
    cudaGetSymbolAddress((void**)&hres, g_hres);
    cudaGetSymbolAddress((void**)&hn,   g_hn);
    cudaGetSymbolAddress((void**)&ff1,  g_ff1);
    cudaGetSymbolAddress((void**)&ff3,  g_ff3);

    // 1. xn = rmsnorm(x, g1)
    rmsnorm_kernel<<<TOKENS, 256>>>(x, g1, xn);

    // 2. q,k,v = xn @ w_{q,k,v}
    dim3 gqkv((D_MODEL + BN - 1) / BN, TOKENS / BM);
    sgemm_kernel<false><<<gqkv, 256>>>(xn, w_q, nullptr, q, TOKENS, D_MODEL, D_MODEL);
    sgemm_kernel<false><<<gqkv, 256>>>(xn, w_k, nullptr, k, TOKENS, D_MODEL, D_MODEL);
    sgemm_kernel<false><<<gqkv, 256>>>(xn, w_v, nullptr, v, TOKENS, D_MODEL, D_MODEL);

    // 3. attention
    dim3 gat(SEQ / AQ_ROWS, BATCH * N_HEADS);
    attention_kernel<<<gat, 256>>>(q, k, v, attn);

    // 4. hres = x + attn @ w_o
    sgemm_kernel<true><<<gqkv, 256>>>(attn, w_o, x, hres, TOKENS, D_MODEL, D_MODEL);

    // 5. hn = rmsnorm(hres, g2)
    rmsnorm_kernel<<<TOKENS, 256>>>(hres, g2, hn);

    // 6. ff1 = hn @ w1 ; ff3 = hn @ w3
    dim3 gff((D_FF + BN - 1) / BN, TOKENS / BM);
    sgemm_kernel<false><<<gff, 256>>>(hn, w1, nullptr, ff1, TOKENS, D_FF, D_MODEL);
    sgemm_kernel<false><<<gff, 256>>>(hn, w3, nullptr, ff3, TOKENS, D_FF, D_MODEL);

    // 7. ff1 = silu(ff1) * ff3
    int n4 = (TOKENS * D_FF) / 4;
    swiglu_kernel<<<(n4 + 255) / 256, 256>>>(ff1, ff3, n4);

    // 8. out = hres + ff1 @ w2
    dim3 go((D_MODEL + BN - 1) / BN, TOKENS / BM);
    sgemm_kernel<true><<<go, 256>>>(ff1, w2, hres, out, TOKENS, D_MODEL, D_FF);
}

// round 9
// speedup vs baseline: 1.6544x; 1.6544x over previous
#include <cuda_runtime.h>
#include <cuda_bf16.h>
#include <cstdint>
#include <math.h>

// Problem constants
#define D_MODEL 1024
#define N_HEADS 16
#define D_HEAD  64
#define D_FF    2752
#define D_FF_P  2816          // padded to multiple of 128
#define BATCH   2
#define SEQ     2048
#define TOKENS  (BATCH * SEQ) // 4096
#define EPSV    1e-5f

typedef __nv_bfloat16 bf16;

// ---------------------------------------------------------------------------
// Scratch buffers (device globals; no allocation allowed)
// ---------------------------------------------------------------------------
__device__ bf16  g_xnh [TOKENS * D_MODEL];
__device__ bf16  g_xnl [TOKENS * D_MODEL];
__device__ float g_q   [TOKENS * D_MODEL];
__device__ float g_k   [TOKENS * D_MODEL];
__device__ float g_v   [TOKENS * D_MODEL];
__device__ bf16  g_ath [TOKENS * D_MODEL];
__device__ bf16  g_atl [TOKENS * D_MODEL];
__device__ float g_hres[TOKENS * D_MODEL];
__device__ bf16  g_hnh [TOKENS * D_MODEL];
__device__ bf16  g_hnl [TOKENS * D_MODEL];
__device__ float g_ff1 [TOKENS * D_FF];
__device__ float g_ff3 [TOKENS * D_FF];
__device__ bf16  g_gh  [TOKENS * D_FF];
__device__ bf16  g_gl  [TOKENS * D_FF];
// Transposed + split weights: T[n][k] = W[k][n]
__device__ bf16  g_wqh[D_MODEL * D_MODEL], g_wql[D_MODEL * D_MODEL];
__device__ bf16  g_wkh[D_MODEL * D_MODEL], g_wkl[D_MODEL * D_MODEL];
__device__ bf16  g_wvh[D_MODEL * D_MODEL], g_wvl[D_MODEL * D_MODEL];
__device__ bf16  g_woh[D_MODEL * D_MODEL], g_wol[D_MODEL * D_MODEL];
__device__ bf16  g_w1h[D_FF_P * D_MODEL],  g_w1l[D_FF_P * D_MODEL];
__device__ bf16  g_w3h[D_FF_P * D_MODEL],  g_w3l[D_FF_P * D_MODEL];
__device__ bf16  g_w2h[D_MODEL * D_FF],    g_w2l[D_MODEL * D_FF];

// ---------------------------------------------------------------------------
// Helpers
// ---------------------------------------------------------------------------
__device__ __forceinline__ uint32_t smem_u32(const void* p) {
    uint32_t a;
    asm("{ .reg .u64 t; cvta.to.shared.u64 t, %1; cvt.u32.u64 %0, t; }" : "=r"(a) : "l"(p));
    return a;
}

#define CP_ASYNC16(dst, src) \
    asm volatile("cp.async.cg.shared.global [%0], [%1], 16;" :: "r"((uint32_t)(dst)), "l"(src) : "memory")
#define CP_COMMIT() asm volatile("cp.async.commit_group;" ::: "memory")
#define CP_WAIT(n)  asm volatile("cp.async.wait_group %0;" :: "n"(n) : "memory")

#define LDSM_X4(r0, r1, r2, r3, addr) \
    asm volatile("ldmatrix.sync.aligned.m8n8.x4.shared.b16 {%0,%1,%2,%3}, [%4];" \
                 : "=r"(r0), "=r"(r1), "=r"(r2), "=r"(r3) : "r"(addr))

#define MMA16816(d, a, b0, b1) \
    asm volatile("mma.sync.aligned.m16n8k16.row.col.f32.bf16.bf16.f32 " \
                 "{%0,%1,%2,%3}, {%4,%5,%6,%7}, {%8,%9}, {%0,%1,%2,%3};" \
                 : "+f"((d)[0]), "+f"((d)[1]), "+f"((d)[2]), "+f"((d)[3]) \
                 : "r"((a)[0]), "r"((a)[1]), "r"((a)[2]), "r"((a)[3]), "r"(b0), "r"(b1))

__device__ __forceinline__ void split2(float v, bf16& h, bf16& l) {
    h = __float2bfloat16(v);
    l = __float2bfloat16(v - __bfloat162float(h));
}

// ---------------------------------------------------------------------------
// Weight transpose + split: W[K,N] fp32 -> Th[Npad,K], Tl[Npad,K] bf16
// ---------------------------------------------------------------------------
__global__ void __launch_bounds__(256) wsplit_kernel(
    const float* __restrict__ W, bf16* __restrict__ Th, bf16* __restrict__ Tl,
    int K, int N)
{
    __shared__ float tile[32][33];
    int n0 = blockIdx.x * 32, k0 = blockIdx.y * 32;
    int tx = threadIdx.x, ty = threadIdx.y;
    #pragma unroll
    for (int i = 0; i < 4; i++) {
        int r = ty + i * 8;
        int n = n0 + tx;
        tile[r][tx] = (n < N) ? W[(size_t)(k0 + r) * N + n] : 0.f;
    }
    __syncthreads();
    #pragma unroll
    for (int i = 0; i < 4; i++) {
        int rn = ty + i * 8;
        int gn = n0 + rn, gk = k0 + tx;
        bf16 h, l;
        split2(tile[tx][rn], h, l);
        Th[(size_t)gn * K + gk] = h;
        Tl[(size_t)gn * K + gk] = l;
    }
}

// ---------------------------------------------------------------------------
// RMSNorm -> split bf16 hi/lo
// ---------------------------------------------------------------------------
__global__ void __launch_bounds__(256) rmsnorm_split_kernel(
    const float* __restrict__ x, const float* __restrict__ g,
    bf16* __restrict__ yh, bf16* __restrict__ yl)
{
    int row = blockIdx.x;
    const float* xr = x + (size_t)row * D_MODEL;
    int t = threadIdx.x;

    float4 v = reinterpret_cast<const float4*>(xr)[t];
    float ss = v.x * v.x + v.y * v.y + v.z * v.z + v.w * v.w;
    #pragma unroll
    for (int o = 16; o > 0; o >>= 1) ss += __shfl_xor_sync(0xffffffffu, ss, o);

    __shared__ float warp_s[8];
    int lane = t & 31, wid = t >> 5;
    if (lane == 0) warp_s[wid] = ss;
    __syncthreads();
    if (wid == 0) {
        float s2 = (lane < 8) ? warp_s[lane] : 0.f;
        #pragma unroll
        for (int o = 4; o > 0; o >>= 1) s2 += __shfl_xor_sync(0xffffffffu, s2, o);
        if (lane == 0) warp_s[0] = s2;
    }
    __syncthreads();
    float inv = rsqrtf(warp_s[0] * (1.0f / D_MODEL) + EPSV);

    float4 gv = reinterpret_cast<const float4*>(g)[t];
    float o0 = v.x * inv * gv.x, o1 = v.y * inv * gv.y;
    float o2 = v.z * inv * gv.z, o3 = v.w * inv * gv.w;
    bf16 h0, l0, h1, l1, h2, l2, h3, l3;
    split2(o0, h0, l0); split2(o1, h1, l1); split2(o2, h2, l2); split2(o3, h3, l3);
    __nv_bfloat162* ph = reinterpret_cast<__nv_bfloat162*>(yh + (size_t)row * D_MODEL);
    __nv_bfloat162* pl = reinterpret_cast<__nv_bfloat162*>(yl + (size_t)row * D_MODEL);
    __nv_bfloat162 a, b;
    a.x = h0; a.y = h1; b.x = h2; b.y = h3;
    ph[t * 2] = a; ph[t * 2 + 1] = b;
    a.x = l0; a.y = l1; b.x = l2; b.y = l3;
    pl[t * 2] = a; pl[t * 2 + 1] = b;
}

// ---------------------------------------------------------------------------
// HMMA bf16-split GEMM: C[M,N] = A @ Bt^T (+R)
//   A  = Ah + Al, [M,K] row-major bf16
//   Bt = Bh + Bl, [Npad,K] row-major bf16 (= B column-major)
// Block tile 128x128, BK=32 halves, 256 threads (8 warps, 4x2),
// warp tile 32(M) x 64(N). Double-buffered cp.async.
// 3 passes: AhBh + AhBl + AlBh.
// ---------------------------------------------------------------------------
#define GBM 128
#define GBN 128
#define GBK 32
#define GSTRIDE 40                      // halves per smem row (32 + 8 pad)
#define GTILE_B (128 * GSTRIDE * 2)     // 10240 bytes per tensor tile
#define GSTAGE_B (4 * GTILE_B)          // 40960 bytes per stage
#define GSMEM (2 * GSTAGE_B)            // 81920 bytes

template<bool ADD_RES>
__global__ void __launch_bounds__(256, 1)
gemm_hmma_kernel(const bf16* __restrict__ Ah, const bf16* __restrict__ Al,
                 const bf16* __restrict__ Bh, const bf16* __restrict__ Bl,
                 const float* __restrict__ R, float* __restrict__ C,
                 int N, int K)
{
    extern __shared__ char smem[];
    const uint32_t sb = smem_u32(smem);
    const int tid = threadIdx.x;
    const int lane = tid & 31;
    const int w = tid >> 5;
    const int wm = w & 3;        // 0..3 -> 32-row slices
    const int wn = w >> 2;       // 0..1 -> 64-col slices
    const int n0 = blockIdx.x * GBN;
    const int m0 = blockIdx.y * GBM;

    const bf16* tensors[4] = { Ah, Al, Bh, Bl };
    const int   rbase[4]   = { m0, m0, n0, n0 };

    float acc[2][8][4];
    #pragma unroll
    for (int i = 0; i < 2; i++)
        #pragma unroll
        for (int j = 0; j < 8; j++)
            #pragma unroll
            for (int q = 0; q < 4; q++) acc[i][j][q] = 0.f;

    const int n_k = K / GBK;

    // async load of one k-tile into stage s
    auto load_tile = [&](int kt, int s) {
        const uint32_t stg = sb + s * GSTAGE_B;
        const int koff = kt * GBK;
        #pragma unroll
        for (int u = 0; u < 8; u++) {
            const int tsr = u >> 1;                    // tensor 0..3
            const int c = tid + (u & 1) * 256;         // 0..511
            const int row = c >> 2;                    // 0..127
            const int ch = c & 3;                      // 16B chunk in row
            const uint32_t dst = stg + tsr * GTILE_B + (row * GSTRIDE) * 2 + ch * 16;
            const char* src = (const char*)(tensors[tsr] +
                               (size_t)(rbase[tsr] + row) * K + koff) + ch * 16;
            CP_ASYNC16(dst, src);
        }
        CP_COMMIT();
    };

    load_tile(0, 0);

    for (int kt = 0; kt < n_k; kt++) {
        if (kt + 1 < n_k) {
            load_tile(kt + 1, (kt + 1) & 1);
            CP_WAIT(1);
        } else {
            CP_WAIT(0);
        }
        __syncthreads();

        const uint32_t stg = sb + (kt & 1) * GSTAGE_B;
        const uint32_t sAh = stg;
        const uint32_t sAl = stg + GTILE_B;
        const uint32_t sBh = stg + 2 * GTILE_B;
        const uint32_t sBl = stg + 3 * GTILE_B;

        #pragma unroll
        for (int ks = 0; ks < 2; ks++) {
            const int kc = ks * 16 + ((lane >> 4) << 3);   // A col (halves)
            uint32_t ah[2][4], al[2][4];
            #pragma unroll
            for (int mi = 0; mi < 2; mi++) {
                const int arow = wm * 32 + mi * 16 + (lane & 15);
                const uint32_t off = (uint32_t)(arow * GSTRIDE + kc) * 2;
                LDSM_X4(ah[mi][0], ah[mi][1], ah[mi][2], ah[mi][3], sAh + off);
                LDSM_X4(al[mi][0], al[mi][1], al[mi][2], al[mi][3], sAl + off);
            }
            uint32_t bh[4][4], bl[4][4];
            const int bk = ks * 16 + ((lane >> 3 & 1) << 3);
            #pragma unroll
            for (int nb = 0; nb < 4; nb++) {
                const int nrow = wn * 64 + nb * 16 + ((lane >> 4) << 3) + (lane & 7);
                const uint32_t off = (uint32_t)(nrow * GSTRIDE + bk) * 2;
                LDSM_X4(bh[nb][0], bh[nb][1], bh[nb][2], bh[nb][3], sBh + off);
                LDSM_X4(bl[nb][0], bl[nb][1], bl[nb][2], bl[nb][3], sBl + off);
            }
            #pragma unroll
            for (int mi = 0; mi < 2; mi++)
                #pragma unroll
                for (int nb = 0; nb < 4; nb++) {
                    MMA16816(acc[mi][nb * 2],     ah[mi], bh[nb][0], bh[nb][1]);
                    MMA16816(acc[mi][nb * 2 + 1], ah[mi], bh[nb][2], bh[nb][3]);
                }
            #pragma unroll
            for (int mi = 0; mi < 2; mi++)
                #pragma unroll
                for (int nb = 0; nb < 4; nb++) {
                    MMA16816(acc[mi][nb * 2],     ah[mi], bl[nb][0], bl[nb][1]);
                    MMA16816(acc[mi][nb * 2 + 1], ah[mi], bl[nb][2], bl[nb][3]);
                }
            #pragma unroll
            for (int mi = 0; mi < 2; mi++)
                #pragma unroll
                for (int nb = 0; nb < 4; nb++) {
                    MMA16816(acc[mi][nb * 2],     al[mi], bh[nb][0], bh[nb][1]);
                    MMA16816(acc[mi][nb * 2 + 1], al[mi], bh[nb][2], bh[nb][3]);
                }
        }
        __syncthreads();
    }

    // epilogue: direct register stores (float2), residual fused
    #pragma unroll
    for (int mi = 0; mi < 2; mi++) {
        const int r0 = m0 + wm * 32 + mi * 16 + (lane >> 2);
        #pragma unroll
        for (int n8 = 0; n8 < 8; n8++) {
            const int col = n0 + wn * 64 + n8 * 8 + ((lane & 3) << 1);
            if (col < N) {
                size_t o0 = (size_t)r0 * N + col;
                size_t o1 = (size_t)(r0 + 8) * N + col;
                float2 v0 = make_float2(acc[mi][n8][0], acc[mi][n8][1]);
                float2 v1 = make_float2(acc[mi][n8][2], acc[mi][n8][3]);
                if (ADD_RES) {
                    float2 r0v = *reinterpret_cast<const float2*>(R + o0);
                    float2 r1v = *reinterpret_cast<const float2*>(R + o1);
                    v0.x += r0v.x; v0.y += r0v.y;
                    v1.x += r1v.x; v1.y += r1v.y;
                }
                *reinterpret_cast<float2*>(C + o0) = v0;
                *reinterpret_cast<float2*>(C + o1) = v1;
            }
        }
    }
}

// ---------------------------------------------------------------------------
// Causal flash attention, fp32; writes split bf16 output.
// ---------------------------------------------------------------------------
#define AQ_ROWS 64
#define AK_TILE 32

__global__ void __launch_bounds__(256) attention_kernel(
    const float* __restrict__ Q, const float* __restrict__ K,
    const float* __restrict__ V, bf16* __restrict__ Oh, bf16* __restrict__ Ol)
{
    __shared__ float Qs[AQ_ROWS][D_HEAD];
    __shared__ float Ks[AK_TILE][D_HEAD + 1];
    __shared__ float Vs[AK_TILE][D_HEAD + 1];

    const int t    = threadIdx.x;
    const int lane = t & 31;
    const int w    = t >> 5;
    const int bh   = blockIdx.y;
    const int b    = bh >> 4;
    const int h    = bh & 15;
    const int q0   = blockIdx.x * AQ_ROWS;

    const float scale = 0.125f;
    const size_t base = ((size_t)b * SEQ) * D_MODEL + (size_t)h * D_HEAD;

    #pragma unroll
    for (int u = 0; u < (AQ_ROWS * D_HEAD) / 256; u++) {
        int idx = t + u * 256;
        int r = idx >> 6, d = idx & 63;
        Qs[r][d] = Q[base + (size_t)(q0 + r) * D_MODEL + d];
    }

    float m[8], l[8], acc0[8], acc1[8];
    #pragma unroll
    for (int i = 0; i < 8; i++) { m[i] = -1e30f; l[i] = 0.f; acc0[i] = 0.f; acc1[i] = 0.f; }

    const int nkt = (q0 >> 5) + 2;

    for (int kt = 0; kt < nkt; kt++) {
        const int kbase = kt * AK_TILE;
        __syncthreads();
        #pragma unroll
        for (int u = 0; u < (AK_TILE * D_HEAD) / 256; u++) {
            int idx = t + u * 256;
            int r = idx >> 6, d = idx & 63;
            size_t gk = base + (size_t)(kbase + r) * D_MODEL + d;
            Ks[r][d] = K[gk];
            Vs[r][d] = V[gk];
        }
        __syncthreads();

        #pragma unroll 1
        for (int i = 0; i < 8; i++) {
            const int r = w * 8 + i;
            const int qrow = q0 + r;
            const float* qp = &Qs[r][0];
            const float* kp = &Ks[lane][0];
            float s = 0.f;
            #pragma unroll
            for (int d = 0; d < D_HEAD; d++) s += qp[d] * kp[d];
            s *= scale;
            if (kbase + lane > qrow) s = -1e30f;

            float mt = s;
            #pragma unroll
            for (int o = 16; o > 0; o >>= 1)
                mt = fmaxf(mt, __shfl_xor_sync(0xffffffffu, mt, o));
            float mnew = fmaxf(m[i], mt);
            float p    = __expf(s - mnew);
            float corr = __expf(m[i] - mnew);
            m[i] = mnew;

            float ps = p;
            #pragma unroll
            for (int o = 16; o > 0; o >>= 1)
                ps += __shfl_xor_sync(0xffffffffu, ps, o);
            l[i] = l[i] * corr + ps;
            acc0[i] *= corr;
            acc1[i] *= corr;

            #pragma unroll
            for (int kk = 0; kk < AK_TILE; kk++) {
                float pk = __shfl_sync(0xffffffffu, p, kk);
                acc0[i] += pk * Vs[kk][lane];
                acc1[i] += pk * Vs[kk][lane + 32];
            }
        }
    }

    #pragma unroll
    for (int i = 0; i < 8; i++) {
        const int r = w * 8 + i;
        float inv = 1.0f / l[i];
        size_t go = base + (size_t)(q0 + r) * D_MODEL;
        bf16 h0, l0, h1, l1;
        split2(acc0[i] * inv, h0, l0);
        split2(acc1[i] * inv, h1, l1);
        Oh[go + lane]      = h0;  Ol[go + lane]      = l0;
        Oh[go + lane + 32] = h1;  Ol[go + lane + 32] = l1;
    }
}

// ---------------------------------------------------------------------------
// SwiGLU -> split bf16
// ---------------------------------------------------------------------------
__global__ void __launch_bounds__(256) swiglu_split_kernel(
    const float* __restrict__ a, const float* __restrict__ b,
    bf16* __restrict__ gh, bf16* __restrict__ gl, int n4)
{
    int i = blockIdx.x * blockDim.x + threadIdx.x;
    if (i >= n4) return;
    float4 va = reinterpret_cast<const float4*>(a)[i];
    float4 vb = reinterpret_cast<const float4*>(b)[i];
    float o0 = va.x / (1.f + __expf(-va.x)) * vb.x;
    float o1 = va.y / (1.f + __expf(-va.y)) * vb.y;
    float o2 = va.z / (1.f + __expf(-va.z)) * vb.z;
    float o3 = va.w / (1.f + __expf(-va.w)) * vb.w;
    bf16 h0, l0, h1, l1, h2, l2, h3, l3;
    split2(o0, h0, l0); split2(o1, h1, l1); split2(o2, h2, l2); split2(o3, h3, l3);
    __nv_bfloat162 p0, p1;
    p0.x = h0; p0.y = h1; p1.x = h2; p1.y = h3;
    reinterpret_cast<__nv_bfloat162*>(gh)[i * 2]     = p0;
    reinterpret_cast<__nv_bfloat162*>(gh)[i * 2 + 1] = p1;
    p0.x = l0; p0.y = l1; p1.x = l2; p1.y = l3;
    reinterpret_cast<__nv_bfloat162*>(gl)[i * 2]     = p0;
    reinterpret_cast<__nv_bfloat162*>(gl)[i * 2 + 1] = p1;
}

// ---------------------------------------------------------------------------
// Launch
// ---------------------------------------------------------------------------
extern "C" void kernel_launch(void* const* d_in, const int* in_sizes, int n_in,
                              void* d_out, int out_size)
{
    const float* x   = (const float*)d_in[0];
    const float* g1  = (const float*)d_in[1];
    const float* g2  = (const float*)d_in[2];
    const float* w_q = (const float*)d_in[3];
    const float* w_k = (const float*)d_in[4];
    const float* w_v = (const float*)d_in[5];
    const float* w_o = (const float*)d_in[6];
    const float* w1  = (const float*)d_in[7];
    const float* w2  = (const float*)d_in[8];
    const float* w3  = (const float*)d_in[9];
    float* out = (float*)d_out;

    bf16 *xnh, *xnl, *ath, *atl, *hnh, *hnl, *gh, *gl;
    float *q, *k, *v, *hres, *ff1, *ff3;
    bf16 *wqh, *wql, *wkh, *wkl, *wvh, *wvl, *woh, *wol;
    bf16 *w1h, *w1l, *w3h, *w3l, *w2h, *w2l;
    cudaGetSymbolAddress((void**)&xnh, g_xnh);  cudaGetSymbolAddress((void**)&xnl, g_xnl);
    cudaGetSymbolAddress((void**)&q,   g_q);    cudaGetSymbolAddress((void**)&k,   g_k);
    cudaGetSymbolAddress((void**)&v,   g_v);
    cudaGetSymbolAddress((void**)&ath, g_ath);  cudaGetSymbolAddress((void**)&atl, g_atl);
    cudaGetSymbolAddress((void**)&hres,g_hres);
    cudaGetSymbolAddress((void**)&hnh, g_hnh);  cudaGetSymbolAddress((void**)&hnl, g_hnl);
    cudaGetSymbolAddress((void**)&ff1, g_ff1);  cudaGetSymbolAddress((void**)&ff3, g_ff3);
    cudaGetSymbolAddress((void**)&gh,  g_gh);   cudaGetSymbolAddress((void**)&gl,  g_gl);
    cudaGetSymbolAddress((void**)&wqh, g_wqh);  cudaGetSymbolAddress((void**)&wql, g_wql);
    cudaGetSymbolAddress((void**)&wkh, g_wkh);  cudaGetSymbolAddress((void**)&wkl, g_wkl);
    cudaGetSymbolAddress((void**)&wvh, g_wvh);  cudaGetSymbolAddress((void**)&wvl, g_wvl);
    cudaGetSymbolAddress((void**)&woh, g_woh);  cudaGetSymbolAddress((void**)&wol, g_wol);
    cudaGetSymbolAddress((void**)&w1h, g_w1h);  cudaGetSymbolAddress((void**)&w1l, g_w1l);
    cudaGetSymbolAddress((void**)&w3h, g_w3h);  cudaGetSymbolAddress((void**)&w3l, g_w3l);
    cudaGetSymbolAddress((void**)&w2h, g_w2h);  cudaGetSymbolAddress((void**)&w2l, g_w2l);

    cudaFuncSetAttribute(gemm_hmma_kernel<false>,
                         cudaFuncAttributeMaxDynamicSharedMemorySize, GSMEM);
    cudaFuncSetAttribute(gemm_hmma_kernel<true>,
                         cudaFuncAttributeMaxDynamicSharedMemorySize, GSMEM);

    // 0. weight transpose + split
    dim3 wt(32, 8);
    wsplit_kernel<<<dim3(D_MODEL / 32, D_MODEL / 32), wt>>>(w_q, wqh, wql, D_MODEL, D_MODEL);
    wsplit_kernel<<<dim3(D_MODEL / 32, D_MODEL / 32), wt>>>(w_k, wkh, wkl, D_MODEL, D_MODEL);
    wsplit_kernel<<<dim3(D_MODEL / 32, D_MODEL / 32), wt>>>(w_v, wvh, wvl, D_MODEL, D_MODEL);
    wsplit_kernel<<<dim3(D_MODEL / 32, D_MODEL / 32), wt>>>(w_o, woh, wol, D_MODEL, D_MODEL);
    wsplit_kernel<<<dim3(D_FF_P / 32, D_MODEL / 32), wt>>>(w1, w1h, w1l, D_MODEL, D_FF);
    wsplit_kernel<<<dim3(D_FF_P / 32, D_MODEL / 32), wt>>>(w3, w3h, w3l, D_MODEL, D_FF);
    wsplit_kernel<<<dim3(D_MODEL / 32, D_FF / 32), wt>>>(w2, w2h, w2l, D_FF, D_MODEL);

    // 1. xn = rmsnorm(x, g1) -> split
    rmsnorm_split_kernel<<<TOKENS, 256>>>(x, g1, xnh, xnl);

    // 2. q,k,v
    dim3 gqkv(D_MODEL / 128, TOKENS / 128);
    gemm_hmma_kernel<false><<<gqkv, 256, GSMEM>>>(xnh, xnl, wqh, wql, nullptr, q, D_MODEL, D_MODEL);
    gemm_hmma_kernel<false><<<gqkv, 256, GSMEM>>>(xnh, xnl, wkh, wkl, nullptr, k, D_MODEL, D_MODEL);
    gemm_hmma_kernel<false><<<gqkv, 256, GSMEM>>>(xnh, xnl, wvh, wvl, nullptr, v, D_MODEL, D_MODEL);

    // 3. attention -> split output
    dim3 gat(SEQ / AQ_ROWS, BATCH * N_HEADS);
    attention_kernel<<<gat, 256>>>(q, k, v, ath, atl);

    // 4. hres = x + attn @ w_o
    gemm_hmma_kernel<true><<<gqkv, 256, GSMEM>>>(ath, atl, woh, wol, x, hres, D_MODEL, D_MODEL);

    // 5. hn = rmsnorm(hres, g2) -> split
    rmsnorm_split_kernel<<<TOKENS, 256>>>(hres, g2, hnh, hnl);

    // 6. ff1 = hn @ w1 ; ff3 = hn @ w3
    dim3 gff(D_FF_P / 128, TOKENS / 128);
    gemm_hmma_kernel<false><<<gff, 256, GSMEM>>>(hnh, hnl, w1h, w1l, nullptr, ff1, D_FF, D_MODEL);
    gemm_hmma_kernel<false><<<gff, 256, GSMEM>>>(hnh, hnl, w3h, w3l, nullptr, ff3, D_FF, D_MODEL);

    // 7. gate
    int n4 = (TOKENS * D_FF) / 4;
    swiglu_split_kernel<<<(n4 + 255) / 256, 256>>>(ff1, ff3, gh, gl, n4);

    // 8. out = hres + gate @ w2
    gemm_hmma_kernel<true><<<gqkv, 256, GSMEM>>>(gh, gl, w2h, w2l, hres, out, D_MODEL, D_FF);
}

// round 11
// speedup vs baseline: 3.2229x; 1.9481x over previous
#include <cuda_runtime.h>
#include <cuda_bf16.h>
#include <cstdint>
#include <math.h>

// Problem constants
#define D_MODEL 1024
#define N_HEADS 16
#define D_HEAD  64
#define D_FF    2752
#define D_FF_P  2816          // padded to multiple of 128
#define BATCH   2
#define SEQ     2048
#define TOKENS  (BATCH * SEQ) // 4096
#define EPSV    1e-5f

typedef __nv_bfloat16 bf16;

// ---------------------------------------------------------------------------
// Scratch buffers (device globals; no allocation allowed)
// ---------------------------------------------------------------------------
__device__ bf16  g_xnh [TOKENS * D_MODEL];
__device__ bf16  g_xnl [TOKENS * D_MODEL];
__device__ bf16  g_qh  [TOKENS * D_MODEL];
__device__ bf16  g_ql  [TOKENS * D_MODEL];
__device__ bf16  g_kh  [TOKENS * D_MODEL];
__device__ bf16  g_kl  [TOKENS * D_MODEL];
__device__ bf16  g_vh  [TOKENS * D_MODEL];
__device__ bf16  g_vl  [TOKENS * D_MODEL];
__device__ bf16  g_ath [TOKENS * D_MODEL];
__device__ bf16  g_atl [TOKENS * D_MODEL];
__device__ float g_hres[TOKENS * D_MODEL];
__device__ bf16  g_hnh [TOKENS * D_MODEL];
__device__ bf16  g_hnl [TOKENS * D_MODEL];
__device__ float g_ff1 [TOKENS * D_FF];
__device__ float g_ff3 [TOKENS * D_FF];
__device__ bf16  g_gh  [TOKENS * D_FF];
__device__ bf16  g_gl  [TOKENS * D_FF];
// Transposed + split weights: T[n][k] = W[k][n]
__device__ bf16  g_wqh[D_MODEL * D_MODEL], g_wql[D_MODEL * D_MODEL];
__device__ bf16  g_wkh[D_MODEL * D_MODEL], g_wkl[D_MODEL * D_MODEL];
__device__ bf16  g_wvh[D_MODEL * D_MODEL], g_wvl[D_MODEL * D_MODEL];
__device__ bf16  g_woh[D_MODEL * D_MODEL], g_wol[D_MODEL * D_MODEL];
__device__ bf16  g_w1h[D_FF_P * D_MODEL],  g_w1l[D_FF_P * D_MODEL];
__device__ bf16  g_w3h[D_FF_P * D_MODEL],  g_w3l[D_FF_P * D_MODEL];
__device__ bf16  g_w2h[D_MODEL * D_FF],    g_w2l[D_MODEL * D_FF];

// ---------------------------------------------------------------------------
// Helpers
// ---------------------------------------------------------------------------
__device__ __forceinline__ uint32_t smem_u32(const void* p) {
    uint32_t a;
    asm("{ .reg .u64 t; cvta.to.shared.u64 t, %1; cvt.u32.u64 %0, t; }" : "=r"(a) : "l"(p));
    return a;
}

#define CP_ASYNC16(dst, src) \
    asm volatile("cp.async.cg.shared.global [%0], [%1], 16;" :: "r"((uint32_t)(dst)), "l"(src) : "memory")
#define CP_COMMIT() asm volatile("cp.async.commit_group;" ::: "memory")
#define CP_WAIT(n)  asm volatile("cp.async.wait_group %0;" :: "n"(n) : "memory")

#define LDSM_X4(r0, r1, r2, r3, addr) \
    asm volatile("ldmatrix.sync.aligned.m8n8.x4.shared.b16 {%0,%1,%2,%3}, [%4];" \
                 : "=r"(r0), "=r"(r1), "=r"(r2), "=r"(r3) : "r"(addr))

#define LDSM_X4_T(r0, r1, r2, r3, addr) \
    asm volatile("ldmatrix.sync.aligned.m8n8.x4.trans.shared.b16 {%0,%1,%2,%3}, [%4];" \
                 : "=r"(r0), "=r"(r1), "=r"(r2), "=r"(r3) : "r"(addr))

#define MMA16816(d, a, b0, b1) \
    asm volatile("mma.sync.aligned.m16n8k16.row.col.f32.bf16.bf16.f32 " \
                 "{%0,%1,%2,%3}, {%4,%5,%6,%7}, {%8,%9}, {%0,%1,%2,%3};" \
                 : "+f"((d)[0]), "+f"((d)[1]), "+f"((d)[2]), "+f"((d)[3]) \
                 : "r"((a)[0]), "r"((a)[1]), "r"((a)[2]), "r"((a)[3]), "r"(b0), "r"(b1))

__device__ __forceinline__ void split2(float v, bf16& h, bf16& l) {
    h = __float2bfloat16(v);
    l = __float2bfloat16(v - __bfloat162float(h));
}

// pack two floats into a bf16x2 hi reg + bf16x2 lo-residual reg
__device__ __forceinline__ uint32_t pack_split(float a, float b, uint32_t& lo) {
    __nv_bfloat162 hi2 = __floats2bfloat162_rn(a, b);
    float ra = a - __low2float(hi2);
    float rb = b - __high2float(hi2);
    __nv_bfloat162 lo2 = __floats2bfloat162_rn(ra, rb);
    lo = *reinterpret_cast<uint32_t*>(&lo2);
    return *reinterpret_cast<uint32_t*>(&hi2);
}

// ---------------------------------------------------------------------------
// Weight transpose + split: W[K,N] fp32 -> Th[Npad,K], Tl[Npad,K] bf16
// ---------------------------------------------------------------------------
__global__ void __launch_bounds__(256) wsplit_kernel(
    const float* __restrict__ W, bf16* __restrict__ Th, bf16* __restrict__ Tl,
    int K, int N)
{
    __shared__ float tile[32][33];
    int n0 = blockIdx.x * 32, k0 = blockIdx.y * 32;
    int tx = threadIdx.x, ty = threadIdx.y;
    #pragma unroll
    for (int i = 0; i < 4; i++) {
        int r = ty + i * 8;
        int n = n0 + tx;
        tile[r][tx] = (n < N) ? W[(size_t)(k0 + r) * N + n] : 0.f;
    }
    __syncthreads();
    #pragma unroll
    for (int i = 0; i < 4; i++) {
        int rn = ty + i * 8;
        int gn = n0 + rn, gk = k0 + tx;
        bf16 h, l;
        split2(tile[tx][rn], h, l);
        Th[(size_t)gn * K + gk] = h;
        Tl[(size_t)gn * K + gk] = l;
    }
}

// ---------------------------------------------------------------------------
// RMSNorm -> split bf16 hi/lo
// ---------------------------------------------------------------------------
__global__ void __launch_bounds__(256) rmsnorm_split_kernel(
    const float* __restrict__ x, const float* __restrict__ g,
    bf16* __restrict__ yh, bf16* __restrict__ yl)
{
    int row = blockIdx.x;
    const float* xr = x + (size_t)row * D_MODEL;
    int t = threadIdx.x;

    float4 v = reinterpret_cast<const float4*>(xr)[t];
    float ss = v.x * v.x + v.y * v.y + v.z * v.z + v.w * v.w;
    #pragma unroll
    for (int o = 16; o > 0; o >>= 1) ss += __shfl_xor_sync(0xffffffffu, ss, o);

    __shared__ float warp_s[8];
    int lane = t & 31, wid = t >> 5;
    if (lane == 0) warp_s[wid] = ss;
    __syncthreads();
    if (wid == 0) {
        float s2 = (lane < 8) ? warp_s[lane] : 0.f;
        #pragma unroll
        for (int o = 4; o > 0; o >>= 1) s2 += __shfl_xor_sync(0xffffffffu, s2, o);
        if (lane == 0) warp_s[0] = s2;
    }
    __syncthreads();
    float inv = rsqrtf(warp_s[0] * (1.0f / D_MODEL) + EPSV);

    float4 gv = reinterpret_cast<const float4*>(g)[t];
    float o0 = v.x * inv * gv.x, o1 = v.y * inv * gv.y;
    float o2 = v.z * inv * gv.z, o3 = v.w * inv * gv.w;
    bf16 h0, l0, h1, l1, h2, l2, h3, l3;
    split2(o0, h0, l0); split2(o1, h1, l1); split2(o2, h2, l2); split2(o3, h3, l3);
    __nv_bfloat162* ph = reinterpret_cast<__nv_bfloat162*>(yh + (size_t)row * D_MODEL);
    __nv_bfloat162* pl = reinterpret_cast<__nv_bfloat162*>(yl + (size_t)row * D_MODEL);
    __nv_bfloat162 a, b;
    a.x = h0; a.y = h1; b.x = h2; b.y = h3;
    ph[t * 2] = a; ph[t * 2 + 1] = b;
    a.x = l0; a.y = l1; b.x = l2; b.y = l3;
    pl[t * 2] = a; pl[t * 2 + 1] = b;
}

// ---------------------------------------------------------------------------
// HMMA bf16-split GEMM: C = A @ Bt^T (+R), 3 passes AhBh+AhBl+AlBh.
// OMODE: 0 = fp32 out, 1 = fp32 out + residual, 2 = split bf16 out (scaled)
// ---------------------------------------------------------------------------
#define GBK 32
#define GSTRIDE 40                      // halves per smem row (32 + 8 pad)
#define GTILE_B (128 * GSTRIDE * 2)     // 10240 bytes per tensor tile
#define GSTAGE_B (4 * GTILE_B)          // 40960 bytes per stage
#define GSMEM (2 * GSTAGE_B)            // 81920 bytes

template<int OMODE>
__global__ void __launch_bounds__(256, 1)
gemm_hmma_kernel(const bf16* __restrict__ Ah, const bf16* __restrict__ Al,
                 const bf16* __restrict__ Bh, const bf16* __restrict__ Bl,
                 const float* __restrict__ R, float* __restrict__ C,
                 bf16* __restrict__ Csh, bf16* __restrict__ Csl, float scale,
                 int N, int K)
{
    extern __shared__ char smem[];
    const uint32_t sb = smem_u32(smem);
    const int tid = threadIdx.x;
    const int lane = tid & 31;
    const int w = tid >> 5;
    const int wm = w & 3;
    const int wn = w >> 2;
    const int n0 = blockIdx.x * 128;
    const int m0 = blockIdx.y * 128;

    const bf16* tensors[4] = { Ah, Al, Bh, Bl };
    const int   rbase[4]   = { m0, m0, n0, n0 };

    float acc[2][8][4];
    #pragma unroll
    for (int i = 0; i < 2; i++)
        #pragma unroll
        for (int j = 0; j < 8; j++)
            #pragma unroll
            for (int q = 0; q < 4; q++) acc[i][j][q] = 0.f;

    const int n_k = K / GBK;

    auto load_tile = [&](int kt, int s) {
        const uint32_t stg = sb + s * GSTAGE_B;
        const int koff = kt * GBK;
        #pragma unroll
        for (int u = 0; u < 8; u++) {
            const int tsr = u >> 1;
            const int c = tid + (u & 1) * 256;
            const int row = c >> 2;
            const int ch = c & 3;
            const uint32_t dst = stg + tsr * GTILE_B + (row * GSTRIDE) * 2 + ch * 16;
            const char* src = (const char*)(tensors[tsr] +
                               (size_t)(rbase[tsr] + row) * K + koff) + ch * 16;
            CP_ASYNC16(dst, src);
        }
        CP_COMMIT();
    };

    load_tile(0, 0);

    for (int kt = 0; kt < n_k; kt++) {
        if (kt + 1 < n_k) {
            load_tile(kt + 1, (kt + 1) & 1);
            CP_WAIT(1);
        } else {
            CP_WAIT(0);
        }
        __syncthreads();

        const uint32_t stg = sb + (kt & 1) * GSTAGE_B;
        const uint32_t sAh = stg;
        const uint32_t sAl = stg + GTILE_B;
        const uint32_t sBh = stg + 2 * GTILE_B;
        const uint32_t sBl = stg + 3 * GTILE_B;

        #pragma unroll
        for (int ks = 0; ks < 2; ks++) {
            const int kc = ks * 16 + ((lane >> 4) << 3);
            uint32_t ah[2][4], al[2][4];
            #pragma unroll
            for (int mi = 0; mi < 2; mi++) {
                const int arow = wm * 32 + mi * 16 + (lane & 15);
                const uint32_t off = (uint32_t)(arow * GSTRIDE + kc) * 2;
                LDSM_X4(ah[mi][0], ah[mi][1], ah[mi][2], ah[mi][3], sAh + off);
                LDSM_X4(al[mi][0], al[mi][1], al[mi][2], al[mi][3], sAl + off);
            }
            uint32_t bh[4][4], bl[4][4];
            const int bk = ks * 16 + ((lane >> 3 & 1) << 3);
            #pragma unroll
            for (int nb = 0; nb < 4; nb++) {
                const int nrow = wn * 64 + nb * 16 + ((lane >> 4) << 3) + (lane & 7);
                const uint32_t off = (uint32_t)(nrow * GSTRIDE + bk) * 2;
                LDSM_X4(bh[nb][0], bh[nb][1], bh[nb][2], bh[nb][3], sBh + off);
                LDSM_X4(bl[nb][0], bl[nb][1], bl[nb][2], bl[nb][3], sBl + off);
            }
            #pragma unroll
            for (int mi = 0; mi < 2; mi++)
                #pragma unroll
                for (int nb = 0; nb < 4; nb++) {
                    MMA16816(acc[mi][nb * 2],     ah[mi], bh[nb][0], bh[nb][1]);
                    MMA16816(acc[mi][nb * 2 + 1], ah[mi], bh[nb][2], bh[nb][3]);
                }
            #pragma unroll
            for (int mi = 0; mi < 2; mi++)
                #pragma unroll
                for (int nb = 0; nb < 4; nb++) {
                    MMA16816(acc[mi][nb * 2],     ah[mi], bl[nb][0], bl[nb][1]);
                    MMA16816(acc[mi][nb * 2 + 1], ah[mi], bl[nb][2], bl[nb][3]);
                }
            #pragma unroll
            for (int mi = 0; mi < 2; mi++)
                #pragma unroll
                for (int nb = 0; nb < 4; nb++) {
                    MMA16816(acc[mi][nb * 2],     al[mi], bh[nb][0], bh[nb][1]);
                    MMA16816(acc[mi][nb * 2 + 1], al[mi], bh[nb][2], bh[nb][3]);
                }
        }
        __syncthreads();
    }

    #pragma unroll
    for (int mi = 0; mi < 2; mi++) {
        const int r0 = m0 + wm * 32 + mi * 16 + (lane >> 2);
        #pragma unroll
        for (int n8 = 0; n8 < 8; n8++) {
            const int col = n0 + wn * 64 + n8 * 8 + ((lane & 3) << 1);
            if (col < N) {
                size_t o0 = (size_t)r0 * N + col;
                size_t o1 = (size_t)(r0 + 8) * N + col;
                if (OMODE == 2) {
                    uint32_t lo0, lo1;
                    uint32_t hi0 = pack_split(acc[mi][n8][0] * scale, acc[mi][n8][1] * scale, lo0);
                    uint32_t hi1 = pack_split(acc[mi][n8][2] * scale, acc[mi][n8][3] * scale, lo1);
                    *reinterpret_cast<uint32_t*>(Csh + o0) = hi0;
                    *reinterpret_cast<uint32_t*>(Csl + o0) = lo0;
                    *reinterpret_cast<uint32_t*>(Csh + o1) = hi1;
                    *reinterpret_cast<uint32_t*>(Csl + o1) = lo1;
                } else {
                    float2 v0 = make_float2(acc[mi][n8][0], acc[mi][n8][1]);
                    float2 v1 = make_float2(acc[mi][n8][2], acc[mi][n8][3]);
                    if (OMODE == 1) {
                        float2 r0v = *reinterpret_cast<const float2*>(R + o0);
                        float2 r1v = *reinterpret_cast<const float2*>(R + o1);
                        v0.x += r0v.x; v0.y += r0v.y;
                        v1.x += r1v.x; v1.y += r1v.y;
                    }
                    *reinterpret_cast<float2*>(C + o0) = v0;
                    *reinterpret_cast<float2*>(C + o1) = v1;
                }
            }
        }
    }
}

// ---------------------------------------------------------------------------
// HMMA causal flash attention (bf16-split, 3-pass QK^T and PV).
// ---------------------------------------------------------------------------
#define AT_STRIDE 72                 // halves per smem row
#define AT_ROWB   144                // bytes per smem row
#define AT_TILE   (64 * AT_ROWB)     // 9216 bytes per tensor tile
#define AT_STAGE  (4 * AT_TILE)      // 36864
#define AT_SMEM   (2 * AT_TILE + 2 * AT_STAGE)  // 92160

__global__ void __launch_bounds__(128, 1) attention_hmma_kernel(
    const bf16* __restrict__ Qh, const bf16* __restrict__ Ql,
    const bf16* __restrict__ Kh, const bf16* __restrict__ Kl,
    const bf16* __restrict__ Vh, const bf16* __restrict__ Vl,
    bf16* __restrict__ Oh, bf16* __restrict__ Ol)
{
    extern __shared__ char smem[];
    const uint32_t sb = smem_u32(smem);
    const int tid  = threadIdx.x;
    const int lane = tid & 31;
    const int w    = tid >> 5;
    const int bh   = blockIdx.y;
    const int b    = bh >> 4;
    const int h    = bh & 15;
    const int q0   = blockIdx.x * 64;

    const size_t hoff = (size_t)(b * SEQ) * D_MODEL + (size_t)h * D_HEAD;

    {
        const bf16* qt[2] = { Qh, Ql };
        #pragma unroll
        for (int u = 0; u < 8; u++) {
            int linear = tid + u * 128;
            int tsr = linear >> 9;
            int c   = linear & 511;
            int row = c >> 3, ch = c & 7;
            uint32_t dst = sb + tsr * AT_TILE + row * AT_ROWB + ch * 16;
            const char* src = (const char*)(qt[tsr] + hoff + (size_t)(q0 + row) * D_MODEL) + ch * 16;
            CP_ASYNC16(dst, src);
        }
        CP_COMMIT(); CP_WAIT(0);
        __syncthreads();
    }

    uint32_t qfh[4][4], qfl[4][4];
    #pragma unroll
    for (int kc = 0; kc < 4; kc++) {
        uint32_t off = (uint32_t)((16 * w + (lane & 15)) * AT_STRIDE
                                  + 16 * kc + ((lane >> 4) << 3)) * 2;
        LDSM_X4(qfh[kc][0], qfh[kc][1], qfh[kc][2], qfh[kc][3], sb + off);
        LDSM_X4(qfl[kc][0], qfl[kc][1], qfl[kc][2], qfl[kc][3], sb + AT_TILE + off);
    }
    __syncthreads();

    float O[8][4];
    #pragma unroll
    for (int j = 0; j < 8; j++)
        #pragma unroll
        for (int e = 0; e < 4; e++) O[j][e] = 0.f;
    float mA = -1e30f, mB = -1e30f, lA = 0.f, lB = 0.f;

    const int nkt = q0 / 64 + 1;
    const uint32_t kvbase = sb + 2 * AT_TILE;

    const bf16* kvt[4] = { Kh, Kl, Vh, Vl };
    auto load_kv = [&](int kt, int s) {
        const uint32_t stg = kvbase + s * AT_STAGE;
        #pragma unroll
        for (int u = 0; u < 16; u++) {
            int linear = tid + u * 128;
            int tsr = linear >> 9;
            int c   = linear & 511;
            int row = c >> 3, ch = c & 7;
            uint32_t dst = stg + tsr * AT_TILE + row * AT_ROWB + ch * 16;
            const char* src = (const char*)(kvt[tsr] + hoff
                               + (size_t)(kt * 64 + row) * D_MODEL) + ch * 16;
            CP_ASYNC16(dst, src);
        }
        CP_COMMIT();
    };

    load_kv(0, 0);

    for (int kt = 0; kt < nkt; kt++) {
        if (kt + 1 < nkt) { load_kv(kt + 1, (kt + 1) & 1); CP_WAIT(1); }
        else              { CP_WAIT(0); }
        __syncthreads();

        const uint32_t stg = kvbase + (kt & 1) * AT_STAGE;
        const uint32_t sKh = stg;
        const uint32_t sKl = stg + AT_TILE;
        const uint32_t sVh = stg + 2 * AT_TILE;
        const uint32_t sVl = stg + 3 * AT_TILE;

        float sc[8][4];
        #pragma unroll
        for (int j = 0; j < 8; j++)
            #pragma unroll
            for (int e = 0; e < 4; e++) sc[j][e] = 0.f;

        #pragma unroll
        for (int kb2 = 0; kb2 < 4; kb2++) {
            uint32_t khf[4][4], klf[4][4];
            #pragma unroll
            for (int kc = 0; kc < 4; kc++) {
                uint32_t off = (uint32_t)((16 * kb2 + ((lane >> 4) << 3) + (lane & 7)) * AT_STRIDE
                                          + 16 * kc + ((lane >> 3 & 1) << 3)) * 2;
                LDSM_X4(khf[kc][0], khf[kc][1], khf[kc][2], khf[kc][3], sKh + off);
                LDSM_X4(klf[kc][0], klf[kc][1], klf[kc][2], klf[kc][3], sKl + off);
            }
            #pragma unroll
            for (int kc = 0; kc < 4; kc++) {
                MMA16816(sc[2 * kb2],     qfh[kc], khf[kc][0], khf[kc][1]);
                MMA16816(sc[2 * kb2 + 1], qfh[kc], khf[kc][2], khf[kc][3]);
                MMA16816(sc[2 * kb2],     qfh[kc], klf[kc][0], klf[kc][1]);
                MMA16816(sc[2 * kb2 + 1], qfh[kc], klf[kc][2], klf[kc][3]);
                MMA16816(sc[2 * kb2],     qfl[kc], khf[kc][0], khf[kc][1]);
                MMA16816(sc[2 * kb2 + 1], qfl[kc], khf[kc][2], khf[kc][3]);
            }
        }

        const int qrA = q0 + 16 * w + (lane >> 2);
        const int qrB = qrA + 8;
        if (kt == nkt - 1) {
            const int kbase = kt * 64;
            #pragma unroll
            for (int j = 0; j < 8; j++) {
                #pragma unroll
                for (int e = 0; e < 2; e++) {
                    int key = kbase + 8 * j + 2 * (lane & 3) + e;
                    if (key > qrA) sc[j][e]     = -1e30f;
                    if (key > qrB) sc[j][2 + e] = -1e30f;
                }
            }
        }

        float mxA = -1e30f, mxB = -1e30f;
        #pragma unroll
        for (int j = 0; j < 8; j++) {
            mxA = fmaxf(mxA, fmaxf(sc[j][0], sc[j][1]));
            mxB = fmaxf(mxB, fmaxf(sc[j][2], sc[j][3]));
        }
        mxA = fmaxf(mxA, __shfl_xor_sync(0xffffffffu, mxA, 1));
        mxA = fmaxf(mxA, __shfl_xor_sync(0xffffffffu, mxA, 2));
        mxB = fmaxf(mxB, __shfl_xor_sync(0xffffffffu, mxB, 1));
        mxB = fmaxf(mxB, __shfl_xor_sync(0xffffffffu, mxB, 2));

        float mnA = fmaxf(mA, mxA), mnB = fmaxf(mB, mxB);
        float corrA = exp2f(mA - mnA), corrB = exp2f(mB - mnB);
        mA = mnA; mB = mnB;

        float sA = 0.f, sB = 0.f;
        #pragma unroll
        for (int j = 0; j < 8; j++) {
            sc[j][0] = exp2f(sc[j][0] - mnA);
            sc[j][1] = exp2f(sc[j][1] - mnA);
            sc[j][2] = exp2f(sc[j][2] - mnB);
            sc[j][3] = exp2f(sc[j][3] - mnB);
            sA += sc[j][0] + sc[j][1];
            sB += sc[j][2] + sc[j][3];
        }
        sA += __shfl_xor_sync(0xffffffffu, sA, 1);
        sA += __shfl_xor_sync(0xffffffffu, sA, 2);
        sB += __shfl_xor_sync(0xffffffffu, sB, 1);
        sB += __shfl_xor_sync(0xffffffffu, sB, 2);
        lA = lA * corrA + sA;
        lB = lB * corrB + sB;

        #pragma unroll
        for (int j = 0; j < 8; j++) {
            O[j][0] *= corrA; O[j][1] *= corrA;
            O[j][2] *= corrB; O[j][3] *= corrB;
        }

        uint32_t pf[4][4], pfl[4][4];
        #pragma unroll
        for (int kc = 0; kc < 4; kc++) {
            int j0 = 2 * kc, j1 = 2 * kc + 1;
            pf[kc][0] = pack_split(sc[j0][0], sc[j0][1], pfl[kc][0]);
            pf[kc][1] = pack_split(sc[j0][2], sc[j0][3], pfl[kc][1]);
            pf[kc][2] = pack_split(sc[j1][0], sc[j1][1], pfl[kc][2]);
            pf[kc][3] = pack_split(sc[j1][2], sc[j1][3], pfl[kc][3]);
        }

        #pragma unroll
        for (int nb16 = 0; nb16 < 4; nb16++) {
            uint32_t vhf[4][4], vlf[4][4];
            #pragma unroll
            for (int kc = 0; kc < 4; kc++) {
                uint32_t off = (uint32_t)((16 * kc + ((lane >> 3 & 1) << 3) + (lane & 7)) * AT_STRIDE
                                          + 16 * nb16 + ((lane >> 4) << 3)) * 2;
                LDSM_X4_T(vhf[kc][0], vhf[kc][1], vhf[kc][2], vhf[kc][3], sVh + off);
                LDSM_X4_T(vlf[kc][0], vlf[kc][1], vlf[kc][2], vlf[kc][3], sVl + off);
            }
            #pragma unroll
            for (int kc = 0; kc < 4; kc++) {
                MMA16816(O[2 * nb16],     pf[kc],  vhf[kc][0], vhf[kc][1]);
                MMA16816(O[2 * nb16 + 1], pf[kc],  vhf[kc][2], vhf[kc][3]);
                MMA16816(O[2 * nb16],     pf[kc],  vlf[kc][0], vlf[kc][1]);
                MMA16816(O[2 * nb16 + 1], pf[kc],  vlf[kc][2], vlf[kc][3]);
                MMA16816(O[2 * nb16],     pfl[kc], vhf[kc][0], vhf[kc][1]);
                MMA16816(O[2 * nb16 + 1], pfl[kc], vhf[kc][2], vhf[kc][3]);
            }
        }
        __syncthreads();
    }

    const float iA = 1.0f / lA, iB = 1.0f / lB;
    const int qrA = q0 + 16 * w + (lane >> 2);
    #pragma unroll
    for (int j = 0; j < 8; j++) {
        int col = 8 * j + 2 * (lane & 3);
        size_t offA = hoff + (size_t)qrA * D_MODEL + col;
        size_t offB = offA + (size_t)8 * D_MODEL;
        uint32_t loA, loB;
        uint32_t hiA = pack_split(O[j][0] * iA, O[j][1] * iA, loA);
        uint32_t hiB = pack_split(O[j][2] * iB, O[j][3] * iB, loB);
        *reinterpret_cast<uint32_t*>(Oh + offA) = hiA;
        *reinterpret_cast<uint32_t*>(Ol + offA) = loA;
        *reinterpret_cast<uint32_t*>(Oh + offB) = hiB;
        *reinterpret_cast<uint32_t*>(Ol + offB) = loB;
    }
}

// ---------------------------------------------------------------------------
// SwiGLU -> split bf16
// ---------------------------------------------------------------------------
__global__ void __launch_bounds__(256) swiglu_split_kernel(
    const float* __restrict__ a, const float* __restrict__ b,
    bf16* __restrict__ gh, bf16* __restrict__ gl, int n4)
{
    int i = blockIdx.x * blockDim.x + threadIdx.x;
    if (i >= n4) return;
    float4 va = reinterpret_cast<const float4*>(a)[i];
    float4 vb = reinterpret_cast<const float4*>(b)[i];
    float o0 = va.x / (1.f + __expf(-va.x)) * vb.x;
    float o1 = va.y / (1.f + __expf(-va.y)) * vb.y;
    float o2 = va.z / (1.f + __expf(-va.z)) * vb.z;
    float o3 = va.w / (1.f + __expf(-va.w)) * vb.w;
    bf16 h0, l0, h1, l1, h2, l2, h3, l3;
    split2(o0, h0, l0); split2(o1, h1, l1); split2(o2, h2, l2); split2(o3, h3, l3);
    __nv_bfloat162 p0, p1;
    p0.x = h0; p0.y = h1; p1.x = h2; p1.y = h3;
    reinterpret_cast<__nv_bfloat162*>(gh)[i * 2]     = p0;
    reinterpret_cast<__nv_bfloat162*>(gh)[i * 2 + 1] = p1;
    p0.x = l0; p0.y = l1; p1.x = l2; p1.y = l3;
    reinterpret_cast<__nv_bfloat162*>(gl)[i * 2]     = p0;
    reinterpret_cast<__nv_bfloat162*>(gl)[i * 2 + 1] = p1;
}

// ---------------------------------------------------------------------------
// Launch
// ---------------------------------------------------------------------------
extern "C" void kernel_launch(void* const* d_in, const int* in_sizes, int n_in,
                              void* d_out, int out_size)
{
    const float* x   = (const float*)d_in[0];
    const float* g1  = (const float*)d_in[1];
    const float* g2  = (const float*)d_in[2];
    const float* w_q = (const float*)d_in[3];
    const float* w_k = (const float*)d_in[4];
    const float* w_v = (const float*)d_in[5];
    const float* w_o = (const float*)d_in[6];
    const float* w1  = (const float*)d_in[7];
    const float* w2  = (const float*)d_in[8];
    const float* w3  = (const float*)d_in[9];
    float* out = (float*)d_out;

    bf16 *xnh, *xnl, *qh, *ql, *kh, *kl, *vh, *vl, *ath, *atl, *hnh, *hnl, *gh, *gl;
    float *hres, *ff1, *ff3;
    bf16 *wqh, *wql, *wkh, *wkl, *wvh, *wvl, *woh, *wol;
    bf16 *w1h, *w1l, *w3h, *w3l, *w2h, *w2l;
    cudaGetSymbolAddress((void**)&xnh, g_xnh);  cudaGetSymbolAddress((void**)&xnl, g_xnl);
    cudaGetSymbolAddress((void**)&qh,  g_qh);   cudaGetSymbolAddress((void**)&ql,  g_ql);
    cudaGetSymbolAddress((void**)&kh,  g_kh);   cudaGetSymbolAddress((void**)&kl,  g_kl);
    cudaGetSymbolAddress((void**)&vh,  g_vh);   cudaGetSymbolAddress((void**)&vl,  g_vl);
    cudaGetSymbolAddress((void**)&ath, g_ath);  cudaGetSymbolAddress((void**)&atl, g_atl);
    cudaGetSymbolAddress((void**)&hres,g_hres);
    cudaGetSymbolAddress((void**)&hnh, g_hnh);  cudaGetSymbolAddress((void**)&hnl, g_hnl);
    cudaGetSymbolAddress((void**)&ff1, g_ff1);  cudaGetSymbolAddress((void**)&ff3, g_ff3);
    cudaGetSymbolAddress((void**)&gh,  g_gh);   cudaGetSymbolAddress((void**)&gl,  g_gl);
    cudaGetSymbolAddress((void**)&wqh, g_wqh);  cudaGetSymbolAddress((void**)&wql, g_wql);
    cudaGetSymbolAddress((void**)&wkh, g_wkh);  cudaGetSymbolAddress((void**)&wkl, g_wkl);
    cudaGetSymbolAddress((void**)&wvh, g_wvh);  cudaGetSymbolAddress((void**)&wvl, g_wvl);
    cudaGetSymbolAddress((void**)&woh, g_woh);  cudaGetSymbolAddress((void**)&wol, g_wol);
    cudaGetSymbolAddress((void**)&w1h, g_w1h);  cudaGetSymbolAddress((void**)&w1l, g_w1l);
    cudaGetSymbolAddress((void**)&w3h, g_w3h);  cudaGetSymbolAddress((void**)&w3l, g_w3l);
    cudaGetSymbolAddress((void**)&w2h, g_w2h);  cudaGetSymbolAddress((void**)&w2l, g_w2l);

    cudaFuncSetAttribute(gemm_hmma_kernel<0>, cudaFuncAttributeMaxDynamicSharedMemorySize, GSMEM);
    cudaFuncSetAttribute(gemm_hmma_kernel<1>, cudaFuncAttributeMaxDynamicSharedMemorySize, GSMEM);
    cudaFuncSetAttribute(gemm_hmma_kernel<2>, cudaFuncAttributeMaxDynamicSharedMemorySize, GSMEM);
    cudaFuncSetAttribute(attention_hmma_kernel, cudaFuncAttributeMaxDynamicSharedMemorySize, AT_SMEM);

    // 0. weight transpose + split
    dim3 wt(32, 8);
    wsplit_kernel<<<dim3(D_MODEL / 32, D_MODEL / 32), wt>>>(w_q, wqh, wql, D_MODEL, D_MODEL);
    wsplit_kernel<<<dim3(D_MODEL / 32, D_MODEL / 32), wt>>>(w_k, wkh, wkl, D_MODEL, D_MODEL);
    wsplit_kernel<<<dim3(D_MODEL / 32, D_MODEL / 32), wt>>>(w_v, wvh, wvl, D_MODEL, D_MODEL);
    wsplit_kernel<<<dim3(D_MODEL / 32, D_MODEL / 32), wt>>>(w_o, woh, wol, D_MODEL, D_MODEL);
    wsplit_kernel<<<dim3(D_FF_P / 32, D_MODEL / 32), wt>>>(w1, w1h, w1l, D_MODEL, D_FF);
    wsplit_kernel<<<dim3(D_FF_P / 32, D_MODEL / 32), wt>>>(w3, w3h, w3l, D_MODEL, D_FF);
    wsplit_kernel<<<dim3(D_MODEL / 32, D_FF / 32), wt>>>(w2, w2h, w2l, D_FF, D_MODEL);

    // 1. xn = rmsnorm(x, g1) -> split
    rmsnorm_split_kernel<<<TOKENS, 256>>>(x, g1, xnh, xnl);

    // 2. q,k,v -> split bf16 directly (Q pre-scaled by 0.125*log2e)
    const float QSCALE = 0.125f * 1.4426950408889634f;
    dim3 gqkv(D_MODEL / 128, TOKENS / 128);
    gemm_hmma_kernel<2><<<gqkv, 256, GSMEM>>>(xnh, xnl, wqh, wql, nullptr, nullptr, qh, ql, QSCALE, D_MODEL, D_MODEL);
    gemm_hmma_kernel<2><<<gqkv, 256, GSMEM>>>(xnh, xnl, wkh, wkl, nullptr, nullptr, kh, kl, 1.0f, D_MODEL, D_MODEL);
    gemm_hmma_kernel<2><<<gqkv, 256, GSMEM>>>(xnh, xnl, wvh, wvl, nullptr, nullptr, vh, vl, 1.0f, D_MODEL, D_MODEL);

    // 3. attention (HMMA) -> split output
    dim3 gat(SEQ / 64, BATCH * N_HEADS);
    attention_hmma_kernel<<<gat, 128, AT_SMEM>>>(qh, ql, kh, kl, vh, vl, ath, atl);

    // 4. hres = x + attn @ w_o
    gemm_hmma_kernel<1><<<gqkv, 256, GSMEM>>>(ath, atl, woh, wol, x, hres, nullptr, nullptr, 1.0f, D_MODEL, D_MODEL);

    // 5. hn = rmsnorm(hres, g2) -> split
    rmsnorm_split_kernel<<<TOKENS, 256>>>(hres, g2, hnh, hnl);

    // 6. ff1 = hn @ w1 ; ff3 = hn @ w3
    dim3 gff(D_FF_P / 128, TOKENS / 128);
    gemm_hmma_kernel<0><<<gff, 256, GSMEM>>>(hnh, hnl, w1h, w1l, nullptr, ff1, nullptr, nullptr, 1.0f, D_FF, D_MODEL);
    gemm_hmma_kernel<0><<<gff, 256, GSMEM>>>(hnh, hnl, w3h, w3l, nullptr, ff3, nullptr, nullptr, 1.0f, D_FF, D_MODEL);

    // 7. gate
    int n4 = (TOKENS * D_FF) / 4;
    swiglu_split_kernel<<<(n4 + 255) / 256, 256>>>(ff1, ff3, gh, gl, n4);

    // 8. out = hres + gate @ w2
    gemm_hmma_kernel<1><<<gqkv, 256, GSMEM>>>(gh, gl, w2h, w2l, hres, out, nullptr, nullptr, 1.0f, D_MODEL, D_FF);
}